// round 1
// baseline (speedup 1.0000x reference)
#include <cuda_runtime.h>

#define BT_ 16384
#define T_ 2048
#define B_ 8
#define H_ 1024
#define I_ 2048
#define N_SSM 16
#define R_ 64
#define M_MLP 2816

// ------------------------- scratch (device globals; no allocation) -----------
__device__ float g_h[BT_ * H_];        // rmsnorm out (reused for 2nd rmsnorm)
__device__ float g_proj[BT_ * 4096];   // in_proj out (reused for gate GEMM out)
__device__ float g_xi[BT_ * I_];       // conv+silu out
__device__ float g_sp[BT_ * 96];       // x_proj out (dt_r | B | C)
__device__ float g_dt[BT_ * I_];       // softplus(dt)
__device__ float g_y[BT_ * I_];        // scan out / gated y
__device__ float g_x2[BT_ * H_];       // mixer residual out
__device__ float g_act[BT_ * M_MLP];   // silu(gate)*up

__device__ __forceinline__ float siluf(float g) {
    return g * (1.0f / (1.0f + __expf(-g)));
}

// ------------------------------- rmsnorm -------------------------------------
__global__ void rmsnorm_kernel(const float* __restrict__ x,
                               const float* __restrict__ w,
                               float* __restrict__ out) {
    int row = blockIdx.x;
    int t = threadIdx.x;  // 256 threads, H=1024 -> one float4 each
    const float4* xr = (const float4*)(x + (size_t)row * H_);
    float4 v = xr[t];
    float ss = v.x * v.x + v.y * v.y + v.z * v.z + v.w * v.w;
#pragma unroll
    for (int o = 16; o > 0; o >>= 1) ss += __shfl_down_sync(0xffffffffu, ss, o);
    __shared__ float red[8];
    if ((t & 31) == 0) red[t >> 5] = ss;
    __syncthreads();
    float tot = red[0] + red[1] + red[2] + red[3] + red[4] + red[5] + red[6] + red[7];
    float scale = rsqrtf(tot * (1.0f / (float)H_) + 1e-5f);
    float4 wv = ((const float4*)w)[t];
    float4 o4;
    o4.x = v.x * scale * wv.x;
    o4.y = v.y * scale * wv.y;
    o4.z = v.z * scale * wv.z;
    o4.w = v.w * scale * wv.w;
    ((float4*)(out + (size_t)row * H_))[t] = o4;
}

// ------------------------------- SGEMM ---------------------------------------
// C[M,N] = A[M,K] @ W[N,K]^T  (both K-contiguous), fp32 with packed f32x2 FMA.
// mode 0: store; 1: softplus(acc + bias[n]); 2: acc + aux[m*N+n];
// 3: acc * silu(aux[m*N+n])
#define BM 128
#define BN 128
#define BK 16

__global__ __launch_bounds__(256) void sgemm_kernel(
    const float* __restrict__ A, int lda,
    const float* __restrict__ W,
    const float* __restrict__ aux,
    float* __restrict__ C,
    int M, int N, int K, int mode) {
    __shared__ float As[2][BK][BM + 4];
    __shared__ float Ws[2][BK][BN + 4];

    const int tid = threadIdx.x;
    const int bm = blockIdx.y * BM;
    const int bn = blockIdx.x * BN;

    const int lr = tid >> 2;          // 0..63
    const int lc = (tid & 3) << 2;    // 0,4,8,12

    const int tx = tid & 15;          // n micro
    const int ty = tid >> 4;          // m micro

    const float* Ag0 = A + (size_t)(bm + lr) * lda + lc;
    const float* Ag1 = A + (size_t)(bm + lr + 64) * lda + lc;
    const int wr0 = bn + lr, wr1 = bn + lr + 64;
    const float* Wg0 = W + (size_t)wr0 * K + lc;
    const float* Wg1 = W + (size_t)wr1 * K + lc;
    const bool w0ok = wr0 < N;
    const bool w1ok = wr1 < N;

    const float4 z4 = make_float4(0.f, 0.f, 0.f, 0.f);
    float4 pa0 = *(const float4*)Ag0;
    float4 pa1 = *(const float4*)Ag1;
    float4 pw0 = w0ok ? *(const float4*)Wg0 : z4;
    float4 pw1 = w1ok ? *(const float4*)Wg1 : z4;

    unsigned long long acc[8][4];
#pragma unroll
    for (int i = 0; i < 8; i++)
#pragma unroll
        for (int j = 0; j < 4; j++) acc[i][j] = 0ull;

    const int nk = K >> 4;
    int buf = 0;

    // store tile 0
    {
        As[buf][lc + 0][lr] = pa0.x; As[buf][lc + 1][lr] = pa0.y;
        As[buf][lc + 2][lr] = pa0.z; As[buf][lc + 3][lr] = pa0.w;
        As[buf][lc + 0][lr + 64] = pa1.x; As[buf][lc + 1][lr + 64] = pa1.y;
        As[buf][lc + 2][lr + 64] = pa1.z; As[buf][lc + 3][lr + 64] = pa1.w;
        Ws[buf][lc + 0][lr] = pw0.x; Ws[buf][lc + 1][lr] = pw0.y;
        Ws[buf][lc + 2][lr] = pw0.z; Ws[buf][lc + 3][lr] = pw0.w;
        Ws[buf][lc + 0][lr + 64] = pw1.x; Ws[buf][lc + 1][lr + 64] = pw1.y;
        Ws[buf][lc + 2][lr + 64] = pw1.z; Ws[buf][lc + 3][lr + 64] = pw1.w;
    }
    __syncthreads();

    for (int kt = 0; kt < nk; ++kt) {
        const bool more = (kt + 1) < nk;
        if (more) {
            pa0 = *(const float4*)(Ag0 + (kt + 1) * BK);
            pa1 = *(const float4*)(Ag1 + (kt + 1) * BK);
            pw0 = w0ok ? *(const float4*)(Wg0 + (kt + 1) * BK) : z4;
            pw1 = w1ok ? *(const float4*)(Wg1 + (kt + 1) * BK) : z4;
        }
#pragma unroll
        for (int k = 0; k < BK; ++k) {
            float4 a0 = *(const float4*)(&As[buf][k][ty * 8]);
            float4 a1 = *(const float4*)(&As[buf][k][ty * 8 + 4]);
            const unsigned long long* wp =
                (const unsigned long long*)(&Ws[buf][k][tx * 8]);
            unsigned long long bv0 = wp[0], bv1 = wp[1], bv2 = wp[2], bv3 = wp[3];
            float av[8];
            av[0] = a0.x; av[1] = a0.y; av[2] = a0.z; av[3] = a0.w;
            av[4] = a1.x; av[5] = a1.y; av[6] = a1.z; av[7] = a1.w;
#pragma unroll
            for (int ii = 0; ii < 8; ii++) {
                unsigned long long ap;
                asm("mov.b64 %0, {%1, %1};" : "=l"(ap) : "r"(__float_as_int(av[ii])));
                asm("fma.rn.f32x2 %0, %1, %2, %0;" : "+l"(acc[ii][0]) : "l"(ap), "l"(bv0));
                asm("fma.rn.f32x2 %0, %1, %2, %0;" : "+l"(acc[ii][1]) : "l"(ap), "l"(bv1));
                asm("fma.rn.f32x2 %0, %1, %2, %0;" : "+l"(acc[ii][2]) : "l"(ap), "l"(bv2));
                asm("fma.rn.f32x2 %0, %1, %2, %0;" : "+l"(acc[ii][3]) : "l"(ap), "l"(bv3));
            }
        }
        if (more) {
            int nb = buf ^ 1;
            As[nb][lc + 0][lr] = pa0.x; As[nb][lc + 1][lr] = pa0.y;
            As[nb][lc + 2][lr] = pa0.z; As[nb][lc + 3][lr] = pa0.w;
            As[nb][lc + 0][lr + 64] = pa1.x; As[nb][lc + 1][lr + 64] = pa1.y;
            As[nb][lc + 2][lr + 64] = pa1.z; As[nb][lc + 3][lr + 64] = pa1.w;
            Ws[nb][lc + 0][lr] = pw0.x; Ws[nb][lc + 1][lr] = pw0.y;
            Ws[nb][lc + 2][lr] = pw0.z; Ws[nb][lc + 3][lr] = pw0.w;
            Ws[nb][lc + 0][lr + 64] = pw1.x; Ws[nb][lc + 1][lr + 64] = pw1.y;
            Ws[nb][lc + 2][lr + 64] = pw1.z; Ws[nb][lc + 3][lr + 64] = pw1.w;
            buf = nb;
            __syncthreads();
        }
    }

    // epilogue
#pragma unroll
    for (int i = 0; i < 8; i++) {
        int row = bm + ty * 8 + i;
        size_t rb = (size_t)row * N;
#pragma unroll
        for (int jp = 0; jp < 4; jp++) {
            int col = bn + tx * 8 + jp * 2;
            if (col >= N) continue;
            unsigned int u0, u1;
            asm("mov.b64 {%0, %1}, %2;" : "=r"(u0), "=r"(u1) : "l"(acc[i][jp]));
            float2 v;
            v.x = __int_as_float(u0);
            v.y = __int_as_float(u1);
            if (mode == 1) {
                float z0 = v.x + aux[col];
                float z1 = v.y + aux[col + 1];
                v.x = fmaxf(z0, 0.f) + log1pf(__expf(-fabsf(z0)));
                v.y = fmaxf(z1, 0.f) + log1pf(__expf(-fabsf(z1)));
            } else if (mode == 2) {
                float2 r = *(const float2*)(aux + rb + col);
                v.x += r.x; v.y += r.y;
            } else if (mode == 3) {
                float2 g = *(const float2*)(aux + rb + col);
                v.x *= siluf(g.x);
                v.y *= siluf(g.y);
            }
            *(float2*)(C + rb + col) = v;
        }
    }
}

// ------------------------- causal depthwise conv + silu ----------------------
// xi[b,t,i] = silu( sum_k proj[b, t-3+k, i] * cw[i,k] + cb[i] ), i in [0, I)
__global__ void conv_silu_kernel(const float* __restrict__ proj,
                                 const float* __restrict__ cw,
                                 const float* __restrict__ cb,
                                 float* __restrict__ xi) {
    int idx = blockIdx.x * blockDim.x + threadIdx.x;  // over BT_*512 (float4 on i)
    int i4 = idx & 511;
    int bt = idx >> 9;
    int t = bt & (T_ - 1);
    const float4* cwv = (const float4*)cw;
    float w[4][4];  // [channel within float4][tap]
#pragma unroll
    for (int c = 0; c < 4; c++) {
        float4 tmp = cwv[i4 * 4 + c];
        w[c][0] = tmp.x; w[c][1] = tmp.y; w[c][2] = tmp.z; w[c][3] = tmp.w;
    }
    float4 cbv = ((const float4*)cb)[i4];
    float acc[4] = {cbv.x, cbv.y, cbv.z, cbv.w};
    const float* base = proj + (size_t)bt * 4096 + i4 * 4;
#pragma unroll
    for (int k = 0; k < 4; ++k) {
        int back = 3 - k;
        if (t >= back) {
            float4 p = *(const float4*)(base - (size_t)back * 4096);
            acc[0] += p.x * w[0][k];
            acc[1] += p.y * w[1][k];
            acc[2] += p.z * w[2][k];
            acc[3] += p.w * w[3][k];
        }
    }
    float4 o;
    o.x = siluf(acc[0]); o.y = siluf(acc[1]);
    o.z = siluf(acc[2]); o.w = siluf(acc[3]);
    ((float4*)xi)[idx] = o;
}

// ------------------------------ selective scan -------------------------------
// 2 channels per warp (16 lanes = 16 states each); B/C staged in smem per chunk.
__global__ __launch_bounds__(256) void scan_kernel(const float* __restrict__ dt,
                                                   const float* __restrict__ sp,
                                                   const float* __restrict__ xi,
                                                   const float* __restrict__ A_log,
                                                   float* __restrict__ y) {
    __shared__ float sBC[64][32];  // [t_local][0..15]=B, [16..31]=C
    int tid = threadIdx.x;
    int warp = tid >> 5, lane = tid & 31;
    int half = lane >> 4, n = lane & 15;
    int chan = blockIdx.x * 16 + warp * 2 + half;  // [0, B_*I_)
    int b = chan >> 11;        // / I_
    int i = chan & (I_ - 1);
    float A = -__expf(__ldg(A_log + i * N_SSM + n));
    size_t rowoff = (size_t)b * T_ * I_ + i;
    size_t spoff = (size_t)b * T_ * 96;
    float s = 0.f;

    for (int t0 = 0; t0 < T_; t0 += 64) {
        __syncthreads();
        // load B,C for 64 timesteps: 64 rows x 32 floats
#pragma unroll
        for (int q = tid; q < 512; q += 256) {
            int r = q >> 3, c = (q & 7) << 2;
            *(float4*)&sBC[r][c] =
                *(const float4*)(sp + spoff + (size_t)(t0 + r) * 96 + 64 + c);
        }
        __syncthreads();
        size_t off = rowoff + (size_t)t0 * I_;
        for (int tl = 0; tl < 64; ++tl, off += I_) {
            float dtv = __ldg(dt + off);
            float xv = __ldg(xi + off);
            float dA = __expf(dtv * A);
            s = fmaf(dA, s, dtv * xv * sBC[tl][n]);
            float yv = s * sBC[tl][16 + n];
            yv += __shfl_down_sync(0xffffffffu, yv, 8, 16);
            yv += __shfl_down_sync(0xffffffffu, yv, 4, 16);
            yv += __shfl_down_sync(0xffffffffu, yv, 2, 16);
            yv += __shfl_down_sync(0xffffffffu, yv, 1, 16);
            if (n == 0) y[off] = yv;
        }
    }
}

// --------------------- y = (y + xi*D) * silu(gate) ---------------------------
__global__ void ypost_kernel(float* __restrict__ y,
                             const float* __restrict__ xi,
                             const float* __restrict__ D,
                             const float* __restrict__ proj) {
    size_t idx = (size_t)blockIdx.x * 256 + threadIdx.x;  // float4 over BT_*I_
    size_t i4 = idx & 511;
    size_t bt = idx >> 9;
    float4 yv = ((float4*)y)[idx];
    float4 xv = ((const float4*)xi)[idx];
    float4 dv = ((const float4*)D)[i4];
    float4 gv = ((const float4*)(proj + bt * 4096 + I_))[i4];
    yv.x = (yv.x + xv.x * dv.x) * siluf(gv.x);
    yv.y = (yv.y + xv.y * dv.y) * siluf(gv.y);
    yv.z = (yv.z + xv.z * dv.z) * siluf(gv.z);
    yv.w = (yv.w + xv.w * dv.w) * siluf(gv.w);
    ((float4*)y)[idx] = yv;
}

// ------------------------------- launch --------------------------------------
extern "C" void kernel_launch(void* const* d_in, const int* in_sizes, int n_in,
                              void* d_out, int out_size) {
    const float* x            = (const float*)d_in[0];
    const float* mixer_norm_w = (const float*)d_in[1];
    const float* in_proj_w    = (const float*)d_in[2];
    const float* conv_w       = (const float*)d_in[3];
    const float* conv_b       = (const float*)d_in[4];
    const float* x_proj_w     = (const float*)d_in[5];
    const float* dt_proj_w    = (const float*)d_in[6];
    const float* dt_proj_b    = (const float*)d_in[7];
    const float* A_log        = (const float*)d_in[8];
    const float* Dv           = (const float*)d_in[9];
    const float* out_proj_w   = (const float*)d_in[10];
    const float* mlp_norm_w   = (const float*)d_in[11];
    const float* gate_w       = (const float*)d_in[12];
    const float* up_w         = (const float*)d_in[13];
    const float* down_w       = (const float*)d_in[14];
    float* out = (float*)d_out;

    float *h, *proj, *xi, *sp, *dt, *y, *x2, *act;
    cudaGetSymbolAddress((void**)&h, g_h);
    cudaGetSymbolAddress((void**)&proj, g_proj);
    cudaGetSymbolAddress((void**)&xi, g_xi);
    cudaGetSymbolAddress((void**)&sp, g_sp);
    cudaGetSymbolAddress((void**)&dt, g_dt);
    cudaGetSymbolAddress((void**)&y, g_y);
    cudaGetSymbolAddress((void**)&x2, g_x2);
    cudaGetSymbolAddress((void**)&act, g_act);

    // 1) h = rmsnorm(x)
    rmsnorm_kernel<<<BT_, 256>>>(x, mixer_norm_w, h);
    // 2) proj = h @ in_proj_w^T   (16384 x 4096 x 1024)
    sgemm_kernel<<<dim3(4096 / BN, BT_ / BM), 256>>>(h, H_, in_proj_w, nullptr,
                                                     proj, BT_, 4096, H_, 0);
    // 3) xi = silu(causal_conv(proj[:, :I]))
    conv_silu_kernel<<<BT_ * 512 / 256, 256>>>(proj, conv_w, conv_b, xi);
    // 4) sp = xi @ x_proj_w^T     (16384 x 96 x 2048)
    sgemm_kernel<<<dim3(1, BT_ / BM), 256>>>(xi, I_, x_proj_w, nullptr, sp, BT_,
                                             96, I_, 0);
    // 5) dt = softplus(sp[:, :64] @ dt_proj_w^T + b)   (16384 x 2048 x 64)
    sgemm_kernel<<<dim3(I_ / BN, BT_ / BM), 256>>>(sp, 96, dt_proj_w, dt_proj_b,
                                                   dt, BT_, I_, R_, 1);
    // 6) selective scan -> y (raw)
    scan_kernel<<<(B_ * I_) / 16, 256>>>(dt, sp, xi, A_log, y);
    // 7) y = (y + xi*D) * silu(gate)
    ypost_kernel<<<BT_ * 512 / 256, 256>>>(y, xi, Dv, proj);
    // 8) x2 = x + y @ out_proj_w^T   (16384 x 1024 x 2048)
    sgemm_kernel<<<dim3(H_ / BN, BT_ / BM), 256>>>(y, I_, out_proj_w, x, x2,
                                                   BT_, H_, I_, 2);
    // 9) h = rmsnorm(x2)
    rmsnorm_kernel<<<BT_, 256>>>(x2, mlp_norm_w, h);
    // 10) proj(reused) = h @ gate_w^T   (16384 x 2816 x 1024)
    sgemm_kernel<<<dim3(M_MLP / BN, BT_ / BM), 256>>>(h, H_, gate_w, nullptr,
                                                      proj, BT_, M_MLP, H_, 0);
    // 11) act = silu(proj) * (h @ up_w^T)
    sgemm_kernel<<<dim3(M_MLP / BN, BT_ / BM), 256>>>(h, H_, up_w, proj, act,
                                                      BT_, M_MLP, H_, 3);
    // 12) out = x2 + act @ down_w^T   (16384 x 1024 x 2816)
    sgemm_kernel<<<dim3(H_ / BN, BT_ / BM), 256>>>(act, M_MLP, down_w, x2, out,
                                                   BT_, H_, M_MLP, 2);
}

// round 4
// speedup vs baseline: 2.1084x; 2.1084x over previous
#include <cuda_runtime.h>
#include <cstdint>

#define BT_ 16384
#define T_ 2048
#define B_ 8
#define H_ 1024
#define I_ 2048
#define N_SSM 16
#define R_ 64
#define M_MLP 2816

__device__ float g_h[BT_ * H_];
__device__ float g_proj[BT_ * 4096];
__device__ float g_xi[BT_ * I_];
__device__ float g_sp[BT_ * 96];
__device__ float g_dt[BT_ * I_];
__device__ float g_y[BT_ * I_];
__device__ float g_x2[BT_ * H_];
__device__ float g_act[BT_ * M_MLP];
__device__ float g_w_in[4096 * H_];
__device__ float g_w_xp[96 * I_];
__device__ float g_w_dt[I_ * R_];
__device__ float g_w_out[H_ * I_];
__device__ float g_w_gate[M_MLP * H_];
__device__ float g_w_up[M_MLP * H_];
__device__ float g_w_down[H_ * M_MLP];

__device__ __forceinline__ float siluf(float g) {
    return g * (1.0f / (1.0f + __expf(-g)));
}
__device__ __forceinline__ float to_tf32(float v) {
    uint32_t r;
    asm("cvt.rna.tf32.f32 %0, %1;" : "=r"(r) : "f"(v));
    return __uint_as_float(r);
}
__device__ __forceinline__ uint32_t smem_u32(const void* p) {
    return (uint32_t)__cvta_generic_to_shared(p);
}
__device__ __forceinline__ void cp4(uint32_t dst, const void* src) {
    asm volatile("cp.async.ca.shared.global [%0], [%1], 4;" ::"r"(dst),
                 "l"(src));
}
#define CP_COMMIT() asm volatile("cp.async.commit_group;" ::: "memory")
#define CP_WAIT2() asm volatile("cp.async.wait_group 2;" ::: "memory")

// mma.sync m16n8k8 tf32: d += a*b
#define MMA8(d, A0, A1, A2, A3, B0, B1)                                        \
    asm volatile(                                                              \
        "mma.sync.aligned.m16n8k8.row.col.f32.tf32.tf32.f32 "                  \
        "{%0,%1,%2,%3},{%4,%5,%6,%7},{%8,%9},{%0,%1,%2,%3};"                   \
        : "+f"((d)[0]), "+f"((d)[1]), "+f"((d)[2]), "+f"((d)[3])               \
        : "r"(__float_as_uint(A0)), "r"(__float_as_uint(A1)),                  \
          "r"(__float_as_uint(A2)), "r"(__float_as_uint(A3)),                  \
          "r"(__float_as_uint(B0)), "r"(__float_as_uint(B1)))

// ------------------------- tf32 mma.sync GEMM --------------------------------
// C[M,N] = A[M,K] @ W[N,K]^T.  BM=BN=128, BK=16, 4 stages, 8 warps (2m x 4n),
// warp tile 64x32. Smem k-permuted: position p holds k=(p>>2)+4*(p&3), applied
// to both A and B (dot product invariant) -> each fragment = one LDS.128.
// mode 0: store tf32; 1: softplus(acc+bias[n]); 2: acc+aux[m*N+n];
// 3: tf32(acc*silu(aux[m*N+n]))
#define STAGES 4
#define STG_FLOATS 4096  // A 2048 + B 2048
#define GEMM_SMEM (STAGES * STG_FLOATS * 4)

__global__ __launch_bounds__(256, 2) void mma_gemm(
    const float* __restrict__ A, int lda, const float* __restrict__ W,
    const float* __restrict__ aux, float* __restrict__ C, int N, int K,
    int mode, int n_valid) {
    extern __shared__ float sm[];
    const int tid = threadIdx.x;
    const int lane = tid & 31, wid = tid >> 5;
    const int wm = wid & 1, wn = wid >> 1;
    const int qr = lane >> 2, qc = lane & 3;
    const int bm = blockIdx.y * 128, bn = blockIdx.x * 128;
    const int nk = K >> 4;

    float acc[4][4][4];
#pragma unroll
    for (int mi = 0; mi < 4; mi++)
#pragma unroll
        for (int ni = 0; ni < 4; ni++)
#pragma unroll
            for (int q = 0; q < 4; q++) acc[mi][ni][q] = 0.f;

    auto load_stage = [&](int s, int kt) {
        float* sA = sm + s * STG_FLOATS;
        float* sB = sA + 2048;
#pragma unroll
        for (int i = 0; i < 8; i++) {
            int w = tid + i * 256;
            int row = w >> 4, kk = w & 15;
            int p = ((kk & 3) << 2) | (kk >> 2);
            cp4(smem_u32(sA + row * 16 + p),
                A + (size_t)(bm + row) * lda + kt * 16 + kk);
        }
#pragma unroll
        for (int i = 0; i < 8; i++) {
            int w = tid + i * 256;
            int row = w >> 4, kk = w & 15;
            int p = ((kk & 3) << 2) | (kk >> 2);
            if (bn + row < n_valid)
                cp4(smem_u32(sB + row * 16 + p),
                    W + (size_t)(bn + row) * (size_t)K + kt * 16 + kk);
        }
    };

    for (int s = 0; s < STAGES - 1; s++) {
        if (s < nk) load_stage(s, s);
        CP_COMMIT();
    }

    for (int kt = 0; kt < nk; kt++) {
        CP_WAIT2();
        __syncthreads();
        int pf = kt + STAGES - 1;
        if (pf < nk) load_stage(pf & 3, pf);
        CP_COMMIT();

        const float* As = sm + (kt & 3) * STG_FLOATS;
        const float* Bs = As + 2048;
        float4 alo[4], ahi[4], bb[4];
#pragma unroll
        for (int mi = 0; mi < 4; mi++) {
            const float* pa = As + (wm * 64 + mi * 16 + qr) * 16 + 4 * qc;
            alo[mi] = *(const float4*)pa;
            ahi[mi] = *(const float4*)(pa + 128);  // +8 rows
        }
#pragma unroll
        for (int ni = 0; ni < 4; ni++)
            bb[ni] = *(const float4*)(Bs + (wn * 32 + ni * 8 + qr) * 16 + 4 * qc);
#pragma unroll
        for (int mi = 0; mi < 4; mi++)
#pragma unroll
            for (int ni = 0; ni < 4; ni++) {
                MMA8(acc[mi][ni], alo[mi].x, ahi[mi].x, alo[mi].y, ahi[mi].y,
                     bb[ni].x, bb[ni].y);
                MMA8(acc[mi][ni], alo[mi].z, ahi[mi].z, alo[mi].w, ahi[mi].w,
                     bb[ni].z, bb[ni].w);
            }
    }

    // epilogue: thread holds (r0,c0),(r0,c0+1),(r0+8,c0),(r0+8,c0+1) per tile
#pragma unroll
    for (int mi = 0; mi < 4; mi++) {
#pragma unroll
        for (int ni = 0; ni < 4; ni++) {
            int r0 = bm + wm * 64 + mi * 16 + qr;
            int c0 = bn + wn * 32 + ni * 8 + 2 * qc;
            if (c0 >= n_valid) continue;
            float v00 = acc[mi][ni][0], v01 = acc[mi][ni][1];
            float v10 = acc[mi][ni][2], v11 = acc[mi][ni][3];
            size_t g0 = (size_t)r0 * (size_t)N + c0;
            size_t g1 = g0 + (size_t)8 * N;
            if (mode == 1) {
                float b0 = __ldg(aux + c0), b1 = __ldg(aux + c0 + 1);
                float z;
                z = v00 + b0; v00 = fmaxf(z, 0.f) + log1pf(__expf(-fabsf(z)));
                z = v01 + b1; v01 = fmaxf(z, 0.f) + log1pf(__expf(-fabsf(z)));
                z = v10 + b0; v10 = fmaxf(z, 0.f) + log1pf(__expf(-fabsf(z)));
                z = v11 + b1; v11 = fmaxf(z, 0.f) + log1pf(__expf(-fabsf(z)));
            } else if (mode == 2) {
                float2 r0v = *(const float2*)(aux + g0);
                float2 r1v = *(const float2*)(aux + g1);
                v00 += r0v.x; v01 += r0v.y;
                v10 += r1v.x; v11 += r1v.y;
            } else if (mode == 3) {
                float2 a0v = *(const float2*)(aux + g0);
                float2 a1v = *(const float2*)(aux + g1);
                v00 = to_tf32(v00 * siluf(a0v.x));
                v01 = to_tf32(v01 * siluf(a0v.y));
                v10 = to_tf32(v10 * siluf(a1v.x));
                v11 = to_tf32(v11 * siluf(a1v.y));
            } else {
                v00 = to_tf32(v00); v01 = to_tf32(v01);
                v10 = to_tf32(v10); v11 = to_tf32(v11);
            }
            *(float2*)(C + g0) = make_float2(v00, v01);
            *(float2*)(C + g1) = make_float2(v10, v11);
        }
    }
}

__global__ void round_tf32_kernel(const float* __restrict__ src,
                                  float* __restrict__ dst, int n4) {
    int i = blockIdx.x * 256 + threadIdx.x;
    if (i < n4) {
        float4 v = ((const float4*)src)[i];
        v.x = to_tf32(v.x); v.y = to_tf32(v.y);
        v.z = to_tf32(v.z); v.w = to_tf32(v.w);
        ((float4*)dst)[i] = v;
    }
}

__global__ void rmsnorm_kernel(const float* __restrict__ x,
                               const float* __restrict__ w,
                               float* __restrict__ out) {
    int row = blockIdx.x;
    int t = threadIdx.x;
    const float4* xr = (const float4*)(x + (size_t)row * H_);
    float4 v = xr[t];
    float ss = v.x * v.x + v.y * v.y + v.z * v.z + v.w * v.w;
#pragma unroll
    for (int o = 16; o > 0; o >>= 1) ss += __shfl_down_sync(0xffffffffu, ss, o);
    __shared__ float red[8];
    if ((t & 31) == 0) red[t >> 5] = ss;
    __syncthreads();
    float tot = red[0] + red[1] + red[2] + red[3] + red[4] + red[5] + red[6] + red[7];
    float scale = rsqrtf(tot * (1.0f / (float)H_) + 1e-5f);
    float4 wv = ((const float4*)w)[t];
    float4 o4;
    o4.x = to_tf32(v.x * scale * wv.x);
    o4.y = to_tf32(v.y * scale * wv.y);
    o4.z = to_tf32(v.z * scale * wv.z);
    o4.w = to_tf32(v.w * scale * wv.w);
    ((float4*)(out + (size_t)row * H_))[t] = o4;
}

__global__ void conv_silu_kernel(const float* __restrict__ proj,
                                 const float* __restrict__ cw,
                                 const float* __restrict__ cb,
                                 float* __restrict__ xi) {
    int idx = blockIdx.x * blockDim.x + threadIdx.x;
    int i4 = idx & 511;
    int bt = idx >> 9;
    int t = bt & (T_ - 1);
    const float4* cwv = (const float4*)cw;
    float w[4][4];
#pragma unroll
    for (int c = 0; c < 4; c++) {
        float4 tmp = cwv[i4 * 4 + c];
        w[c][0] = tmp.x; w[c][1] = tmp.y; w[c][2] = tmp.z; w[c][3] = tmp.w;
    }
    float4 cbv = ((const float4*)cb)[i4];
    float acc[4] = {cbv.x, cbv.y, cbv.z, cbv.w};
    const float* base = proj + (size_t)bt * 4096 + i4 * 4;
#pragma unroll
    for (int k = 0; k < 4; ++k) {
        int back = 3 - k;
        if (t >= back) {
            float4 p = *(const float4*)(base - (size_t)back * 4096);
            acc[0] += p.x * w[0][k];
            acc[1] += p.y * w[1][k];
            acc[2] += p.z * w[2][k];
            acc[3] += p.w * w[3][k];
        }
    }
    float4 o;
    o.x = to_tf32(siluf(acc[0]));
    o.y = to_tf32(siluf(acc[1]));
    o.z = to_tf32(siluf(acc[2]));
    o.w = to_tf32(siluf(acc[3]));
    ((float4*)xi)[idx] = o;
}

__global__ __launch_bounds__(256) void scan_kernel(
    const float* __restrict__ dt, const float* __restrict__ sp,
    const float* __restrict__ xi, const float* __restrict__ A_log,
    float* __restrict__ y) {
    __shared__ float sBC[64][32];
    int tid = threadIdx.x;
    int warp = tid >> 5, lane = tid & 31;
    int half = lane >> 4, n = lane & 15;
    int chan = blockIdx.x * 16 + warp * 2 + half;
    int b = chan >> 11;
    int i = chan & (I_ - 1);
    float A = -__expf(__ldg(A_log + i * N_SSM + n));
    size_t rowoff = (size_t)b * T_ * I_ + i;
    size_t spoff = (size_t)b * T_ * 96;
    float s = 0.f;

    for (int t0 = 0; t0 < T_; t0 += 64) {
        __syncthreads();
#pragma unroll
        for (int q = tid; q < 512; q += 256) {
            int r = q >> 3, c = (q & 7) << 2;
            *(float4*)&sBC[r][c] =
                *(const float4*)(sp + spoff + (size_t)(t0 + r) * 96 + 64 + c);
        }
        __syncthreads();
        size_t off = rowoff + (size_t)t0 * I_;
        for (int tl = 0; tl < 64; ++tl, off += I_) {
            float dtv = __ldg(dt + off);
            float xv = __ldg(xi + off);
            float dA = __expf(dtv * A);
            s = fmaf(dA, s, dtv * xv * sBC[tl][n]);
            float yv = s * sBC[tl][16 + n];
            yv += __shfl_down_sync(0xffffffffu, yv, 8, 16);
            yv += __shfl_down_sync(0xffffffffu, yv, 4, 16);
            yv += __shfl_down_sync(0xffffffffu, yv, 2, 16);
            yv += __shfl_down_sync(0xffffffffu, yv, 1, 16);
            if (n == 0) y[off] = yv;
        }
    }
}

__global__ void ypost_kernel(float* __restrict__ y,
                             const float* __restrict__ xi,
                             const float* __restrict__ D,
                             const float* __restrict__ proj) {
    size_t idx = (size_t)blockIdx.x * 256 + threadIdx.x;
    size_t i4 = idx & 511;
    size_t bt = idx >> 9;
    float4 yv = ((float4*)y)[idx];
    float4 xv = ((const float4*)xi)[idx];
    float4 dv = ((const float4*)D)[i4];
    float4 gv = ((const float4*)(proj + bt * 4096 + I_))[i4];
    yv.x = to_tf32((yv.x + xv.x * dv.x) * siluf(gv.x));
    yv.y = to_tf32((yv.y + xv.y * dv.y) * siluf(gv.y));
    yv.z = to_tf32((yv.z + xv.z * dv.z) * siluf(gv.z));
    yv.w = to_tf32((yv.w + xv.w * dv.w) * siluf(gv.w));
    ((float4*)y)[idx] = yv;
}

extern "C" void kernel_launch(void* const* d_in, const int* in_sizes, int n_in,
                              void* d_out, int out_size) {
    const float* x            = (const float*)d_in[0];
    const float* mixer_norm_w = (const float*)d_in[1];
    const float* in_proj_w    = (const float*)d_in[2];
    const float* conv_w       = (const float*)d_in[3];
    const float* conv_b       = (const float*)d_in[4];
    const float* x_proj_w     = (const float*)d_in[5];
    const float* dt_proj_w    = (const float*)d_in[6];
    const float* dt_proj_b    = (const float*)d_in[7];
    const float* A_log        = (const float*)d_in[8];
    const float* Dv           = (const float*)d_in[9];
    const float* out_proj_w   = (const float*)d_in[10];
    const float* mlp_norm_w   = (const float*)d_in[11];
    const float* gate_w       = (const float*)d_in[12];
    const float* up_w         = (const float*)d_in[13];
    const float* down_w       = (const float*)d_in[14];
    float* out = (float*)d_out;

    float *h, *proj, *xi, *sp, *dt, *y, *x2, *act;
    float *w_in, *w_xp, *w_dt, *w_out, *w_gate, *w_up, *w_down;
    cudaGetSymbolAddress((void**)&h, g_h);
    cudaGetSymbolAddress((void**)&proj, g_proj);
    cudaGetSymbolAddress((void**)&xi, g_xi);
    cudaGetSymbolAddress((void**)&sp, g_sp);
    cudaGetSymbolAddress((void**)&dt, g_dt);
    cudaGetSymbolAddress((void**)&y, g_y);
    cudaGetSymbolAddress((void**)&x2, g_x2);
    cudaGetSymbolAddress((void**)&act, g_act);
    cudaGetSymbolAddress((void**)&w_in, g_w_in);
    cudaGetSymbolAddress((void**)&w_xp, g_w_xp);
    cudaGetSymbolAddress((void**)&w_dt, g_w_dt);
    cudaGetSymbolAddress((void**)&w_out, g_w_out);
    cudaGetSymbolAddress((void**)&w_gate, g_w_gate);
    cudaGetSymbolAddress((void**)&w_up, g_w_up);
    cudaGetSymbolAddress((void**)&w_down, g_w_down);

    cudaFuncSetAttribute(mma_gemm, cudaFuncAttributeMaxDynamicSharedMemorySize,
                         GEMM_SMEM);

    round_tf32_kernel<<<4096, 256>>>(in_proj_w, w_in, 4096 * H_ / 4);
    round_tf32_kernel<<<192, 256>>>(x_proj_w, w_xp, 96 * I_ / 4);
    round_tf32_kernel<<<128, 256>>>(dt_proj_w, w_dt, I_ * R_ / 4);
    round_tf32_kernel<<<2048, 256>>>(out_proj_w, w_out, H_ * I_ / 4);
    round_tf32_kernel<<<2816, 256>>>(gate_w, w_gate, M_MLP * H_ / 4);
    round_tf32_kernel<<<2816, 256>>>(up_w, w_up, M_MLP * H_ / 4);
    round_tf32_kernel<<<2816, 256>>>(down_w, w_down, H_ * M_MLP / 4);

    rmsnorm_kernel<<<BT_, 256>>>(x, mixer_norm_w, h);
    // proj = h @ in_proj^T   (16384 x 4096 x 1024)
    mma_gemm<<<dim3(32, 128), 256, GEMM_SMEM>>>(h, H_, w_in, nullptr, proj,
                                                4096, H_, 0, 4096);
    conv_silu_kernel<<<BT_ * 512 / 256, 256>>>(proj, conv_w, conv_b, xi);
    // sp = xi @ x_proj^T     (16384 x 96 x 2048)
    mma_gemm<<<dim3(1, 128), 256, GEMM_SMEM>>>(xi, I_, w_xp, nullptr, sp, 96,
                                               I_, 0, 96);
    // dt = softplus(sp[:,:64] @ dt_proj^T + b)   (16384 x 2048 x 64)
    mma_gemm<<<dim3(16, 128), 256, GEMM_SMEM>>>(sp, 96, w_dt, dt_proj_b, dt,
                                                I_, R_, 1, I_);
    scan_kernel<<<(B_ * I_) / 16, 256>>>(dt, sp, xi, A_log, y);
    ypost_kernel<<<BT_ * 512 / 256, 256>>>(y, xi, Dv, proj);
    // x2 = x + y @ out_proj^T   (16384 x 1024 x 2048)
    mma_gemm<<<dim3(8, 128), 256, GEMM_SMEM>>>(y, I_, w_out, x, x2, H_, I_, 2,
                                               H_);
    rmsnorm_kernel<<<BT_, 256>>>(x2, mlp_norm_w, h);
    // gate = h @ gate_w^T   (16384 x 2816 x 1024)
    mma_gemm<<<dim3(22, 128), 256, GEMM_SMEM>>>(h, H_, w_gate, nullptr, proj,
                                                M_MLP, H_, 0, M_MLP);
    // act = silu(gate) * (h @ up_w^T)
    mma_gemm<<<dim3(22, 128), 256, GEMM_SMEM>>>(h, H_, w_up, proj, act, M_MLP,
                                                H_, 3, M_MLP);
    // out = x2 + act @ down_w^T   (16384 x 1024 x 2816)
    mma_gemm<<<dim3(8, 128), 256, GEMM_SMEM>>>(act, M_MLP, w_down, x2, out,
                                               H_, M_MLP, 2, H_);
}

// round 5
// speedup vs baseline: 3.3922x; 1.6089x over previous
#include <cuda_runtime.h>
#include <cuda_fp16.h>
#include <cstdint>

#define BT_ 16384
#define T_ 2048
#define B_ 8
#define H_ 1024
#define I_ 2048
#define N_SSM 16
#define R_ 64
#define M_MLP 2816

// ------------------------- scratch (device globals) --------------------------
__device__ __half g_h[BT_ * H_];          // rmsnorm out (half, GEMM A)
__device__ float  g_proj[BT_ * 4096];     // in_proj / gate GEMM out (fp32)
__device__ __half g_xi[BT_ * I_];         // conv+silu out (half)
__device__ float  g_sp[BT_ * 96];         // x_proj out fp32 (scan B/C)
__device__ __half g_sp_h[BT_ * 96];       // x_proj out half (dt GEMM A)
__device__ float  g_dt[BT_ * I_];         // softplus dt (fp32, scan)
__device__ float  g_y[BT_ * I_];          // scan out fp32
__device__ __half g_y_h[BT_ * I_];        // gated y half (out_proj A)
__device__ float  g_x2[BT_ * H_];         // mixer residual out
__device__ __half g_act[BT_ * M_MLP];     // silu(gate)*up (half, down A)
__device__ __half g_w_in[4096 * H_];
__device__ __half g_w_xp[96 * I_];
__device__ __half g_w_dt[I_ * R_];
__device__ __half g_w_out[H_ * I_];
__device__ __half g_w_gate[M_MLP * H_];
__device__ __half g_w_up[M_MLP * H_];
__device__ __half g_w_down[H_ * M_MLP];

__device__ __forceinline__ float siluf(float g) {
    return g * (1.0f / (1.0f + __expf(-g)));
}
__device__ __forceinline__ uint32_t smem_u32(const void* p) {
    return (uint32_t)__cvta_generic_to_shared(p);
}
__device__ __forceinline__ void cp4(uint32_t dst, const void* src) {
    asm volatile("cp.async.ca.shared.global [%0], [%1], 4;" ::"r"(dst), "l"(src));
}
#define CP_COMMIT() asm volatile("cp.async.commit_group;" ::: "memory")
#define CP_WAIT2() asm volatile("cp.async.wait_group 2;" ::: "memory")

// mma.sync m16n8k16 f16 -> f32 accum
#define MMA16(d, a0, a1, a2, a3, b0, b1)                                       \
    asm volatile(                                                              \
        "mma.sync.aligned.m16n8k16.row.col.f32.f16.f16.f32 "                   \
        "{%0,%1,%2,%3},{%4,%5,%6,%7},{%8,%9},{%0,%1,%2,%3};"                   \
        : "+f"((d)[0]), "+f"((d)[1]), "+f"((d)[2]), "+f"((d)[3])               \
        : "r"(a0), "r"(a1), "r"(a2), "r"(a3), "r"(b0), "r"(b1))

// ------------------------- fp16 mma.sync GEMM --------------------------------
// C[M,N] = A[M,K] @ W[N,K]^T, A/W half K-major. BM=BN=128, BK=32, 4 stages,
// 8 warps (2m x 4n), warp tile 64x32.
// Smem row = 32 halfs (64B), k-pair-permuted: pair kp stored at pair-pos
// pp = 4*(kp&3) + ((kp>>2)&1) + 2*(kp>>3). One LDS.128 at (row, qc*16B)
// yields halfs {2qc,2qc+1, 2qc+8,2qc+9, 2qc+16,2qc+17, 2qc+24,2qc+25} =
// exactly the m16n8k16 fragment k-slices for both k-steps.
// mode 0: C fp32 (+Ch half if non-null); 1: softplus(acc+aux[n]) -> C;
// 2: acc + aux[m*N+n] -> C; 3: half(acc * silu(aux[m*N+n])) -> Ch
#define STAGES 4
#define STG_U32 4096  // A 2048 + B 2048 (u32 units)
#define GEMM_SMEM (STAGES * STG_U32 * 4)

__global__ __launch_bounds__(256, 2) void hgemm(
    const __half* __restrict__ A, int lda, const __half* __restrict__ W,
    const float* __restrict__ aux, float* __restrict__ C,
    __half* __restrict__ Ch, int N, int K, int mode, int n_valid) {
    extern __shared__ uint32_t sm[];
    const int tid = threadIdx.x;
    const int lane = tid & 31, wid = tid >> 5;
    const int wm = wid & 1, wn = wid >> 1;
    const int qr = lane >> 2, qc = lane & 3;
    const int bm = blockIdx.y * 128, bn = blockIdx.x * 128;
    const int nk = K >> 5;

    float acc[4][4][4];
#pragma unroll
    for (int mi = 0; mi < 4; mi++)
#pragma unroll
        for (int ni = 0; ni < 4; ni++)
#pragma unroll
            for (int q = 0; q < 4; q++) acc[mi][ni][q] = 0.f;

    auto load_stage = [&](int s, int kt) {
        uint32_t* sA = sm + s * STG_U32;
        uint32_t* sB = sA + 2048;
#pragma unroll
        for (int i = 0; i < 8; i++) {
            int w = tid + i * 256;
            int row = w >> 4, kp = w & 15;
            int pp = 4 * (kp & 3) + ((kp >> 2) & 1) + 2 * (kp >> 3);
            cp4(smem_u32(sA + row * 16 + pp),
                A + (size_t)(bm + row) * lda + kt * 32 + 2 * kp);
        }
#pragma unroll
        for (int i = 0; i < 8; i++) {
            int w = tid + i * 256;
            int row = w >> 4, kp = w & 15;
            int pp = 4 * (kp & 3) + ((kp >> 2) & 1) + 2 * (kp >> 3);
            if (bn + row < n_valid)
                cp4(smem_u32(sB + row * 16 + pp),
                    W + (size_t)(bn + row) * (size_t)K + kt * 32 + 2 * kp);
        }
    };

    for (int s = 0; s < STAGES - 1; s++) {
        if (s < nk) load_stage(s, s);
        CP_COMMIT();
    }

    for (int kt = 0; kt < nk; kt++) {
        CP_WAIT2();
        __syncthreads();
        int pf = kt + STAGES - 1;
        if (pf < nk) load_stage(pf & 3, pf);
        CP_COMMIT();

        const uint32_t* As = sm + (kt & 3) * STG_U32;
        const uint32_t* Bs = As + 2048;
        uint4 alo[4], ahi[4], bb[4];
#pragma unroll
        for (int mi = 0; mi < 4; mi++) {
            int r = wm * 64 + mi * 16 + qr;
            alo[mi] = *(const uint4*)(As + r * 16 + qc * 4);
            ahi[mi] = *(const uint4*)(As + (r + 8) * 16 + qc * 4);
        }
#pragma unroll
        for (int ni = 0; ni < 4; ni++) {
            int r = wn * 32 + ni * 8 + qr;
            bb[ni] = *(const uint4*)(Bs + r * 16 + qc * 4);
        }
#pragma unroll
        for (int mi = 0; mi < 4; mi++)
#pragma unroll
            for (int ni = 0; ni < 4; ni++) {
                MMA16(acc[mi][ni], alo[mi].x, ahi[mi].x, alo[mi].y, ahi[mi].y,
                      bb[ni].x, bb[ni].y);
                MMA16(acc[mi][ni], alo[mi].z, ahi[mi].z, alo[mi].w, ahi[mi].w,
                      bb[ni].z, bb[ni].w);
            }
    }

    // epilogue: thread holds (r0,c0),(r0,c0+1),(r0+8,c0),(r0+8,c0+1) per tile
#pragma unroll
    for (int mi = 0; mi < 4; mi++) {
#pragma unroll
        for (int ni = 0; ni < 4; ni++) {
            int r0 = bm + wm * 64 + mi * 16 + qr;
            int c0 = bn + wn * 32 + ni * 8 + 2 * qc;
            if (c0 >= n_valid) continue;
            float v00 = acc[mi][ni][0], v01 = acc[mi][ni][1];
            float v10 = acc[mi][ni][2], v11 = acc[mi][ni][3];
            size_t g0 = (size_t)r0 * (size_t)N + c0;
            size_t g1 = g0 + (size_t)8 * N;
            if (mode == 1) {
                float b0 = __ldg(aux + c0), b1 = __ldg(aux + c0 + 1);
                float z;
                z = v00 + b0; v00 = fmaxf(z, 0.f) + log1pf(__expf(-fabsf(z)));
                z = v01 + b1; v01 = fmaxf(z, 0.f) + log1pf(__expf(-fabsf(z)));
                z = v10 + b0; v10 = fmaxf(z, 0.f) + log1pf(__expf(-fabsf(z)));
                z = v11 + b1; v11 = fmaxf(z, 0.f) + log1pf(__expf(-fabsf(z)));
                *(float2*)(C + g0) = make_float2(v00, v01);
                *(float2*)(C + g1) = make_float2(v10, v11);
            } else if (mode == 2) {
                float2 r0v = *(const float2*)(aux + g0);
                float2 r1v = *(const float2*)(aux + g1);
                *(float2*)(C + g0) = make_float2(v00 + r0v.x, v01 + r0v.y);
                *(float2*)(C + g1) = make_float2(v10 + r1v.x, v11 + r1v.y);
            } else if (mode == 3) {
                float2 a0v = *(const float2*)(aux + g0);
                float2 a1v = *(const float2*)(aux + g1);
                *(__half2*)(Ch + g0) =
                    __floats2half2_rn(v00 * siluf(a0v.x), v01 * siluf(a0v.y));
                *(__half2*)(Ch + g1) =
                    __floats2half2_rn(v10 * siluf(a1v.x), v11 * siluf(a1v.y));
            } else {
                *(float2*)(C + g0) = make_float2(v00, v01);
                *(float2*)(C + g1) = make_float2(v10, v11);
                if (Ch != nullptr) {
                    *(__half2*)(Ch + g0) = __floats2half2_rn(v00, v01);
                    *(__half2*)(Ch + g1) = __floats2half2_rn(v10, v11);
                }
            }
        }
    }
}

// --------------------------- fp32 -> fp16 convert ----------------------------
__global__ void to_half_kernel(const float* __restrict__ src,
                               __half* __restrict__ dst, int n4) {
    int i = blockIdx.x * 256 + threadIdx.x;
    if (i < n4) {
        float4 v = ((const float4*)src)[i];
        __half2 h0 = __floats2half2_rn(v.x, v.y);
        __half2 h1 = __floats2half2_rn(v.z, v.w);
        uint2 o;
        o.x = *(uint32_t*)&h0;
        o.y = *(uint32_t*)&h1;
        ((uint2*)dst)[i] = o;
    }
}

// ------------------------------- rmsnorm (-> half) ---------------------------
__global__ void rmsnorm_kernel(const float* __restrict__ x,
                               const float* __restrict__ w,
                               __half* __restrict__ out) {
    int row = blockIdx.x;
    int t = threadIdx.x;
    const float4* xr = (const float4*)(x + (size_t)row * H_);
    float4 v = xr[t];
    float ss = v.x * v.x + v.y * v.y + v.z * v.z + v.w * v.w;
#pragma unroll
    for (int o = 16; o > 0; o >>= 1) ss += __shfl_down_sync(0xffffffffu, ss, o);
    __shared__ float red[8];
    if ((t & 31) == 0) red[t >> 5] = ss;
    __syncthreads();
    float tot = red[0] + red[1] + red[2] + red[3] + red[4] + red[5] + red[6] + red[7];
    float scale = rsqrtf(tot * (1.0f / (float)H_) + 1e-5f);
    float4 wv = ((const float4*)w)[t];
    __half2 h0 = __floats2half2_rn(v.x * scale * wv.x, v.y * scale * wv.y);
    __half2 h1 = __floats2half2_rn(v.z * scale * wv.z, v.w * scale * wv.w);
    uint2 o;
    o.x = *(uint32_t*)&h0;
    o.y = *(uint32_t*)&h1;
    ((uint2*)(out + (size_t)row * H_))[t] = o;
}

// ------------------------- causal depthwise conv + silu (-> half) ------------
__global__ void conv_silu_kernel(const float* __restrict__ proj,
                                 const float* __restrict__ cw,
                                 const float* __restrict__ cb,
                                 __half* __restrict__ xi) {
    int idx = blockIdx.x * blockDim.x + threadIdx.x;
    int i4 = idx & 511;
    int bt = idx >> 9;
    int t = bt & (T_ - 1);
    const float4* cwv = (const float4*)cw;
    float w[4][4];
#pragma unroll
    for (int c = 0; c < 4; c++) {
        float4 tmp = cwv[i4 * 4 + c];
        w[c][0] = tmp.x; w[c][1] = tmp.y; w[c][2] = tmp.z; w[c][3] = tmp.w;
    }
    float4 cbv = ((const float4*)cb)[i4];
    float acc[4] = {cbv.x, cbv.y, cbv.z, cbv.w};
    const float* base = proj + (size_t)bt * 4096 + i4 * 4;
#pragma unroll
    for (int k = 0; k < 4; ++k) {
        int back = 3 - k;
        if (t >= back) {
            float4 p = *(const float4*)(base - (size_t)back * 4096);
            acc[0] += p.x * w[0][k];
            acc[1] += p.y * w[1][k];
            acc[2] += p.z * w[2][k];
            acc[3] += p.w * w[3][k];
        }
    }
    __half2 h0 = __floats2half2_rn(siluf(acc[0]), siluf(acc[1]));
    __half2 h1 = __floats2half2_rn(siluf(acc[2]), siluf(acc[3]));
    uint2 o;
    o.x = *(uint32_t*)&h0;
    o.y = *(uint32_t*)&h1;
    ((uint2*)xi)[idx] = o;
}

// ------------------------------ selective scan -------------------------------
__global__ __launch_bounds__(256) void scan_kernel(
    const float* __restrict__ dt, const float* __restrict__ sp,
    const __half* __restrict__ xi, const float* __restrict__ A_log,
    float* __restrict__ y) {
    __shared__ float sBC[64][32];
    int tid = threadIdx.x;
    int warp = tid >> 5, lane = tid & 31;
    int half_ = lane >> 4, n = lane & 15;
    int chan = blockIdx.x * 16 + warp * 2 + half_;
    int b = chan >> 11;
    int i = chan & (I_ - 1);
    float A = -__expf(__ldg(A_log + i * N_SSM + n));
    size_t rowoff = (size_t)b * T_ * I_ + i;
    size_t spoff = (size_t)b * T_ * 96;
    float s = 0.f;

    for (int t0 = 0; t0 < T_; t0 += 64) {
        __syncthreads();
#pragma unroll
        for (int q = tid; q < 512; q += 256) {
            int r = q >> 3, c = (q & 7) << 2;
            *(float4*)&sBC[r][c] =
                *(const float4*)(sp + spoff + (size_t)(t0 + r) * 96 + 64 + c);
        }
        __syncthreads();
        size_t off = rowoff + (size_t)t0 * I_;
        for (int tl = 0; tl < 64; ++tl, off += I_) {
            float dtv = __ldg(dt + off);
            float xv = __half2float(__ldg(xi + off));
            float dA = __expf(dtv * A);
            s = fmaf(dA, s, dtv * xv * sBC[tl][n]);
            float yv = s * sBC[tl][16 + n];
            yv += __shfl_down_sync(0xffffffffu, yv, 8, 16);
            yv += __shfl_down_sync(0xffffffffu, yv, 4, 16);
            yv += __shfl_down_sync(0xffffffffu, yv, 2, 16);
            yv += __shfl_down_sync(0xffffffffu, yv, 1, 16);
            if (n == 0) y[off] = yv;
        }
    }
}

// --------------------- y_h = half((y + xi*D) * silu(gate)) -------------------
__global__ void ypost_kernel(const float* __restrict__ y,
                             const __half* __restrict__ xi,
                             const float* __restrict__ D,
                             const float* __restrict__ proj,
                             __half* __restrict__ yh) {
    size_t idx = (size_t)blockIdx.x * 256 + threadIdx.x;
    size_t i4 = idx & 511;
    size_t bt = idx >> 9;
    float4 yv = ((const float4*)y)[idx];
    uint2 xr = ((const uint2*)xi)[idx];
    __half2 x0 = *(__half2*)&xr.x;
    __half2 x1 = *(__half2*)&xr.y;
    float4 dv = ((const float4*)D)[i4];
    float4 gv = ((const float4*)(proj + bt * 4096 + I_))[i4];
    float o0 = (yv.x + __low2float(x0) * dv.x) * siluf(gv.x);
    float o1 = (yv.y + __high2float(x0) * dv.y) * siluf(gv.y);
    float o2 = (yv.z + __low2float(x1) * dv.z) * siluf(gv.z);
    float o3 = (yv.w + __high2float(x1) * dv.w) * siluf(gv.w);
    __half2 h0 = __floats2half2_rn(o0, o1);
    __half2 h1 = __floats2half2_rn(o2, o3);
    uint2 o;
    o.x = *(uint32_t*)&h0;
    o.y = *(uint32_t*)&h1;
    ((uint2*)yh)[idx] = o;
}

// ------------------------------- launch --------------------------------------
extern "C" void kernel_launch(void* const* d_in, const int* in_sizes, int n_in,
                              void* d_out, int out_size) {
    const float* x            = (const float*)d_in[0];
    const float* mixer_norm_w = (const float*)d_in[1];
    const float* in_proj_w    = (const float*)d_in[2];
    const float* conv_w       = (const float*)d_in[3];
    const float* conv_b       = (const float*)d_in[4];
    const float* x_proj_w     = (const float*)d_in[5];
    const float* dt_proj_w    = (const float*)d_in[6];
    const float* dt_proj_b    = (const float*)d_in[7];
    const float* A_log        = (const float*)d_in[8];
    const float* Dv           = (const float*)d_in[9];
    const float* out_proj_w   = (const float*)d_in[10];
    const float* mlp_norm_w   = (const float*)d_in[11];
    const float* gate_w       = (const float*)d_in[12];
    const float* up_w         = (const float*)d_in[13];
    const float* down_w       = (const float*)d_in[14];
    float* out = (float*)d_out;

    __half *h, *xi, *sp_h, *y_h, *act;
    float *proj, *sp, *dt, *y, *x2;
    __half *w_in, *w_xp, *w_dt, *w_out, *w_gate, *w_up, *w_down;
    cudaGetSymbolAddress((void**)&h, g_h);
    cudaGetSymbolAddress((void**)&proj, g_proj);
    cudaGetSymbolAddress((void**)&xi, g_xi);
    cudaGetSymbolAddress((void**)&sp, g_sp);
    cudaGetSymbolAddress((void**)&sp_h, g_sp_h);
    cudaGetSymbolAddress((void**)&dt, g_dt);
    cudaGetSymbolAddress((void**)&y, g_y);
    cudaGetSymbolAddress((void**)&y_h, g_y_h);
    cudaGetSymbolAddress((void**)&x2, g_x2);
    cudaGetSymbolAddress((void**)&act, g_act);
    cudaGetSymbolAddress((void**)&w_in, g_w_in);
    cudaGetSymbolAddress((void**)&w_xp, g_w_xp);
    cudaGetSymbolAddress((void**)&w_dt, g_w_dt);
    cudaGetSymbolAddress((void**)&w_out, g_w_out);
    cudaGetSymbolAddress((void**)&w_gate, g_w_gate);
    cudaGetSymbolAddress((void**)&w_up, g_w_up);
    cudaGetSymbolAddress((void**)&w_down, g_w_down);

    cudaFuncSetAttribute(hgemm, cudaFuncAttributeMaxDynamicSharedMemorySize,
                         GEMM_SMEM);

    to_half_kernel<<<4096, 256>>>(in_proj_w, w_in, 4096 * H_ / 4);
    to_half_kernel<<<192, 256>>>(x_proj_w, w_xp, 96 * I_ / 4);
    to_half_kernel<<<128, 256>>>(dt_proj_w, w_dt, I_ * R_ / 4);
    to_half_kernel<<<2048, 256>>>(out_proj_w, w_out, H_ * I_ / 4);
    to_half_kernel<<<2816, 256>>>(gate_w, w_gate, M_MLP * H_ / 4);
    to_half_kernel<<<2816, 256>>>(up_w, w_up, M_MLP * H_ / 4);
    to_half_kernel<<<2816, 256>>>(down_w, w_down, H_ * M_MLP / 4);

    rmsnorm_kernel<<<BT_, 256>>>(x, mixer_norm_w, h);
    // proj = h @ in_proj^T   (16384 x 4096 x 1024)
    hgemm<<<dim3(32, 128), 256, GEMM_SMEM>>>(h, H_, w_in, nullptr, proj,
                                             nullptr, 4096, H_, 0, 4096);
    conv_silu_kernel<<<BT_ * 512 / 256, 256>>>(proj, conv_w, conv_b, xi);
    // sp = xi @ x_proj^T     (16384 x 96 x 2048), dual fp32+half out
    hgemm<<<dim3(1, 128), 256, GEMM_SMEM>>>(xi, I_, w_xp, nullptr, sp, sp_h,
                                            96, I_, 0, 96);
    // dt = softplus(sp[:,:64] @ dt_proj^T + b)   (16384 x 2048 x 64)
    hgemm<<<dim3(16, 128), 256, GEMM_SMEM>>>(sp_h, 96, w_dt, dt_proj_b, dt,
                                             nullptr, I_, R_, 1, I_);
    scan_kernel<<<(B_ * I_) / 16, 256>>>(dt, sp, xi, A_log, y);
    ypost_kernel<<<BT_ * 512 / 256, 256>>>(y, xi, Dv, proj, y_h);
    // x2 = x + y @ out_proj^T   (16384 x 1024 x 2048)
    hgemm<<<dim3(8, 128), 256, GEMM_SMEM>>>(y_h, I_, w_out, x, x2, nullptr,
                                            H_, I_, 2, H_);
    rmsnorm_kernel<<<BT_, 256>>>(x2, mlp_norm_w, h);
    // gate = h @ gate_w^T   (16384 x 2816 x 1024)
    hgemm<<<dim3(22, 128), 256, GEMM_SMEM>>>(h, H_, w_gate, nullptr, proj,
                                             nullptr, M_MLP, H_, 0, M_MLP);
    // act = half(silu(gate) * (h @ up_w^T))
    hgemm<<<dim3(22, 128), 256, GEMM_SMEM>>>(h, H_, w_up, proj, nullptr, act,
                                             M_MLP, H_, 3, M_MLP);
    // out = x2 + act @ down_w^T   (16384 x 1024 x 2816)
    hgemm<<<dim3(8, 128), 256, GEMM_SMEM>>>(act, M_MLP, w_down, x2, out,
                                            nullptr, H_, M_MLP, 2, H_);
}